// round 16
// baseline (speedup 1.0000x reference)
#include <cuda_runtime.h>
#include <cuda_fp16.h>
#include <cstdint>

#define EMB 512
#define BATCH 8
#define SEQ 2048
#define TOK (BATCH * SEQ)   // 16384

// Scratch (allocation-free rule: __device__ globals)
__device__ __half g_Xh[(size_t)TOK * EMB];
__device__ __half g_QKV[(size_t)TOK * 3 * EMB];
__device__ __half g_O[(size_t)TOK * EMB];
__device__ __half g_S[(size_t)BATCH * SEQ * SEQ];
__device__ __half g_WT[4 * EMB * EMB];
__device__ float  g_Bqkv[3 * EMB];
__device__ float  g_Lpart[32 * TOK];

// ---------------- PTX helpers (compute_103-safe) ----------------
__device__ __forceinline__ uint32_t smem_u32(const void* p) {
    uint32_t a;
    asm("{ .reg .u64 t; cvta.to.shared.u64 t, %1; cvt.u32.u64 %0, t; }" : "=r"(a) : "l"(p));
    return a;
}
__device__ __forceinline__ void cp16(uint32_t s, const void* g) {
    asm volatile("cp.async.cg.shared.global [%0], [%1], 16;" :: "r"(s), "l"(g));
}
#define CP_COMMIT() asm volatile("cp.async.commit_group;" ::: "memory")
#define CP_WAIT0()  asm volatile("cp.async.wait_group 0;" ::: "memory")

#define LDSM4(r0, r1, r2, r3, addr)                                            \
    asm volatile("ldmatrix.sync.aligned.m8n8.x4.shared.b16 {%0,%1,%2,%3}, [%4];" \
        : "=r"(r0), "=r"(r1), "=r"(r2), "=r"(r3) : "r"(addr))

#define LDSM4_T(r0, r1, r2, r3, addr)                                          \
    asm volatile("ldmatrix.sync.aligned.m8n8.x4.trans.shared.b16 {%0,%1,%2,%3}, [%4];" \
        : "=r"(r0), "=r"(r1), "=r"(r2), "=r"(r3) : "r"(addr))

// FMA-pipe exp (no MUFU): x ~ [-16,16], rel err ~2e-6.
__device__ __forceinline__ float fexp(float x) {
    float t = x * 1.4426950408889634f;
    float r = rintf(t);
    float f = t - r;
    float p =          1.3333558146428443e-3f;
    p = fmaf(p, f,     9.6181291076284772e-3f);
    p = fmaf(p, f,     5.5504108664821580e-2f);
    p = fmaf(p, f,     2.4022650695910071e-1f);
    p = fmaf(p, f,     6.9314718055994531e-1f);
    p = fmaf(p, f,     1.0f);
    int i = (int)r;
    return p * __int_as_float((i + 127) << 23);
}

// fp16 MMA m16n8k16, fp32 accumulate.
__device__ __forceinline__ void mma_f16(float* d, const uint32_t* a, uint32_t b0, uint32_t b1) {
    asm volatile(
        "mma.sync.aligned.m16n8k16.row.col.f32.f16.f16.f32 "
        "{%0,%1,%2,%3}, {%4,%5,%6,%7}, {%8,%9}, {%0,%1,%2,%3};"
        : "+f"(d[0]), "+f"(d[1]), "+f"(d[2]), "+f"(d[3])
        : "r"(a[0]), "r"(a[1]), "r"(a[2]), "r"(a[3]), "r"(b0), "r"(b1));
}

// ---------------- NT fp16 GEMM (ldmatrix, 64x64 warp tiles) ----------------
// C = scale * A @ B' (+epilogue). A [M,lda] halves, K-major.
// BTRANS=false: B [N,ldb] K-major (NT; non-trans LDSM, stride-72 smem).
// BTRANS=true:  B [K,ldb] N-major (NN; V's natural layout; trans LDSM,
//               stride-136 smem -> rows 272B apart, conflict-free).
// Block tile 128x128, BK=64, 4 warps (2x2), 2-stage cp.async, 2 CTAs/SM.
// EPI: 0 = +bias, ->half (QKV)   1 = exp, row-partial-sums, ->half (score)
//      2 = *invl[row] (computed INLINE from Lpart), ->half (AV)
//      3 = +bias, ->float (final)
#define BK 64
#define STR 72
#define STRV 136
#define TILE_HALFS (128 * STR)               // 9216 (>= 64*136=8704 for BTRANS B)
#define STAGE_HALFS (2 * TILE_HALFS)         // 18432
#define SMEM_BYTES (2 * STAGE_HALFS * 2)     // 73728

template <int EPI, bool BTRANS>
__global__ void __launch_bounds__(128, 2) gemm_nt(
    const __half* __restrict__ A, const __half* __restrict__ B,
    const float* __restrict__ aux, void* __restrict__ Cv,
    int lda, int ldb, int ldc, int K,
    size_t sA, size_t sB, size_t sC, int sAux, float scale)
{
    extern __shared__ __half smem[];
    const uint32_t sbase = smem_u32(smem);

    const int tid  = threadIdx.x;
    const int lane = tid & 31;
    const int warp = tid >> 5;
    const int wr = (warp & 1) * 64;
    const int wc = (warp >> 1) * 64;

    const int b = blockIdx.z;
    A += (size_t)b * sA;
    B += (size_t)b * sB;
    const int row0 = blockIdx.y * 128;
    const int col0 = blockIdx.x * 128;

    float acc[4][8][4];
    #pragma unroll
    for (int mi = 0; mi < 4; mi++)
        #pragma unroll
        for (int ni = 0; ni < 8; ni++)
            #pragma unroll
            for (int j = 0; j < 4; j++) acc[mi][ni][j] = 0.0f;

    const __half* gA = A + (size_t)row0 * lda;
    const __half* gB = BTRANS ? (B + col0) : (B + (size_t)col0 * ldb);

    auto fill = [&](int t, int buf) {
        uint32_t smA = sbase + (uint32_t)buf * STAGE_HALFS * 2;
        uint32_t smB = smA + TILE_HALFS * 2;
        const __half* pa = gA + t * BK;
        {   // A: 128 rows x 64 halves (128B rows)
            const int frow0 = tid >> 3;
            const int cq    = tid & 7;
            int row = frow0;
            #pragma unroll
            for (int it = 0; it < 8; it++, row += 16) {
                uint32_t off = 2u * (uint32_t)(row * STR + cq * 8);
                cp16(smA + off, pa + (size_t)row * lda + cq * 8);
            }
        }
        if (BTRANS) {
            // B: 64 k-rows x 128 halves (256B rows), stride STRV
            const __half* pb = B + (size_t)(t * BK) * ldb + col0;
            #pragma unroll
            for (int it = 0; it < 8; it++) {
                int idx = tid + it * 128;         // 0..1023
                int row = idx >> 4, cq = idx & 15;
                uint32_t off = 2u * (uint32_t)(row * STRV + cq * 8);
                cp16(smB + off, pb + (size_t)row * ldb + cq * 8);
            }
        } else {
            const __half* pb = gB + t * BK;
            const int frow0 = tid >> 3;
            const int cq    = tid & 7;
            int row = frow0;
            #pragma unroll
            for (int it = 0; it < 8; it++, row += 16) {
                uint32_t off = 2u * (uint32_t)(row * STR + cq * 8);
                cp16(smB + off, pb + (size_t)row * ldb + cq * 8);
            }
        }
    };

    const int ktiles = K / BK;
    fill(0, 0); CP_COMMIT();

    const int g = lane >> 2;
    const int q = lane & 3;
    const int l8 = lane & 7;
    const int jj = lane >> 3;

    // EPI==2: compute invl for this thread's 8 rows inline from Lpart
    // (identical summation order to the old rowsum_final kernel -> bitwise
    //  identical; overlapped with the first cp.async fill).
    float il[4][2];
    if (EPI == 2) {
        #pragma unroll
        for (int mi = 0; mi < 4; mi++) {
            int grow = b * SEQ + row0 + wr + mi * 16 + g;
            float s0 = 0.0f, s1 = 0.0f;
            #pragma unroll
            for (int i = 0; i < 32; i++) {
                s0 += g_Lpart[(size_t)i * TOK + grow];
                s1 += g_Lpart[(size_t)i * TOK + grow + 8];
            }
            il[mi][0] = 1.0f / s0;
            il[mi][1] = 1.0f / s1;
        }
    }

    uint32_t aOff[4];
    #pragma unroll
    for (int mi = 0; mi < 4; mi++) {
        int row = wr + mi * 16 + (jj & 1) * 8 + l8;
        aOff[mi] = 2u * (uint32_t)(row * STR + (jj >> 1) * 8);
    }
    // B fragment offsets: matrix j covers n in +(j>>1)*8, k in +(j&1)*8.
    uint32_t bOff[4];
    #pragma unroll
    for (int p = 0; p < 4; p++) {
        int nb = wc + p * 16 + (jj >> 1) * 8;
        if (BTRANS) {
            int krow = (jj & 1) * 8 + l8;
            bOff[p] = 2u * (uint32_t)(krow * STRV + nb);
        } else {
            bOff[p] = 2u * (uint32_t)((nb + l8) * STR + (jj & 1) * 8);
        }
    }

    for (int t = 0; t < ktiles; t++) {
        CP_WAIT0();
        __syncthreads();
        if (t + 1 < ktiles) { fill(t + 1, (t + 1) & 1); CP_COMMIT(); }

        const uint32_t smA = sbase + (uint32_t)(t & 1) * STAGE_HALFS * 2;
        const uint32_t smB = smA + TILE_HALFS * 2;

        #pragma unroll
        for (int ks = 0; ks < 4; ks++) {
            const uint32_t kaddA = (uint32_t)ks * 32;            // 16 halves
            const uint32_t kaddB = BTRANS ? (uint32_t)ks * STRV * 32 : (uint32_t)ks * 32;
            uint32_t a[4][4], bb[4][4];
            #pragma unroll
            for (int mi = 0; mi < 4; mi++)
                LDSM4(a[mi][0], a[mi][1], a[mi][2], a[mi][3], smA + aOff[mi] + kaddA);
            #pragma unroll
            for (int p = 0; p < 4; p++) {
                if (BTRANS) LDSM4_T(bb[p][0], bb[p][1], bb[p][2], bb[p][3], smB + bOff[p] + kaddB);
                else        LDSM4  (bb[p][0], bb[p][1], bb[p][2], bb[p][3], smB + bOff[p] + kaddB);
            }
            #pragma unroll
            for (int p = 0; p < 4; p++)
                #pragma unroll
                for (int mi = 0; mi < 4; mi++) {
                    mma_f16(acc[mi][2 * p],     a[mi], bb[p][0], bb[p][1]);
                    mma_f16(acc[mi][2 * p + 1], a[mi], bb[p][2], bb[p][3]);
                }
        }
    }

    // Epilogue
    float rs0[4], rs1[4];
    #pragma unroll
    for (int mi = 0; mi < 4; mi++) { rs0[mi] = 0.0f; rs1[mi] = 0.0f; }

    #pragma unroll
    for (int mi = 0; mi < 4; mi++) {
        int rloc = wr + mi * 16 + g;
        int r = row0 + rloc;
        float il0 = 1.0f, il1 = 1.0f;
        if (EPI == 2) { il0 = il[mi][0]; il1 = il[mi][1]; }
        #pragma unroll
        for (int ni = 0; ni < 8; ni++) {
            int c = wc + ni * 8 + 2 * q;
            float2 v0, v1;
            v0.x = acc[mi][ni][0] * scale;
            v0.y = acc[mi][ni][1] * scale;
            v1.x = acc[mi][ni][2] * scale;
            v1.y = acc[mi][ni][3] * scale;
            if (EPI == 0 || EPI == 3) {
                float bx = aux[col0 + c], by = aux[col0 + c + 1];
                v0.x += bx; v0.y += by;
                v1.x += bx; v1.y += by;
            }
            if (EPI == 1) {
                v0.x = fexp(v0.x); v0.y = fexp(v0.y);
                v1.x = fexp(v1.x); v1.y = fexp(v1.y);
                rs0[mi] += v0.x + v0.y;
                rs1[mi] += v1.x + v1.y;
            }
            if (EPI == 2) {
                v0.x *= il0; v0.y *= il0;
                v1.x *= il1; v1.y *= il1;
            }
            if (EPI == 3) {
                float* c0 = (float*)Cv + (size_t)b * sC + (size_t)r * ldc + col0;
                float* c1 = c0 + (size_t)8 * ldc;
                *reinterpret_cast<float2*>(c0 + c) = v0;
                *reinterpret_cast<float2*>(c1 + c) = v1;
            } else {
                __half* c0 = (__half*)Cv + (size_t)b * sC + (size_t)r * ldc + col0;
                __half* c1 = c0 + (size_t)8 * ldc;
                *reinterpret_cast<__half2*>(c0 + c) = __floats2half2_rn(v0.x, v0.y);
                *reinterpret_cast<__half2*>(c1 + c) = __floats2half2_rn(v1.x, v1.y);
            }
        }
    }

    if (EPI == 1) {
        #pragma unroll
        for (int mi = 0; mi < 4; mi++) {
            rs0[mi] += __shfl_xor_sync(0xFFFFFFFF, rs0[mi], 1);
            rs0[mi] += __shfl_xor_sync(0xFFFFFFFF, rs0[mi], 2);
            rs1[mi] += __shfl_xor_sync(0xFFFFFFFF, rs1[mi], 1);
            rs1[mi] += __shfl_xor_sync(0xFFFFFFFF, rs1[mi], 2);
        }
        if (q == 0) {
            int slot = blockIdx.x * 2 + (warp >> 1);
            size_t base = (size_t)slot * TOK + (size_t)b * SEQ + row0 + wr;
            #pragma unroll
            for (int mi = 0; mi < 4; mi++) {
                g_Lpart[base + mi * 16 + g]     = rs0[mi];
                g_Lpart[base + mi * 16 + g + 8] = rs1[mi];
            }
        }
    }
}

// -------- fused prep: x->fp16 copy, 4 weight transposes, bias concat --------
// grid layout (flat blockIdx.x, 256 threads):
//   [0, 4096)        : round_h   (8 floats/thread)
//   [4096, 5120)     : transpose 32x32 tiles of W[z] (z = block/256)
//   [5120, 5126)     : concat_bias
__global__ void __launch_bounds__(256) prep(
    const float* __restrict__ x, __half* __restrict__ Xh,
    const float* __restrict__ w0, const float* __restrict__ w1,
    const float* __restrict__ w2, const float* __restrict__ w3,
    __half* __restrict__ WT,
    const float* __restrict__ bq, const float* __restrict__ bk,
    const float* __restrict__ bv, float* __restrict__ Bqkv)
{
    __shared__ float t[32][33];
    const int bid = blockIdx.x;
    const int tid = threadIdx.x;

    if (bid < 4096) {
        size_t i = ((size_t)bid * 256 + tid) * 8;
        float4 v0 = *reinterpret_cast<const float4*>(x + i);
        float4 v1 = *reinterpret_cast<const float4*>(x + i + 4);
        __half2 h[4];
        h[0] = __floats2half2_rn(v0.x, v0.y);
        h[1] = __floats2half2_rn(v0.z, v0.w);
        h[2] = __floats2half2_rn(v1.x, v1.y);
        h[3] = __floats2half2_rn(v1.z, v1.w);
        *reinterpret_cast<uint4*>(Xh + i) = *reinterpret_cast<uint4*>(h);
    } else if (bid < 5120) {
        int b2 = bid - 4096;
        int z = b2 >> 8;
        int rem = b2 & 255;
        int bx = rem & 15, by = rem >> 4;
        const float* in = (z == 0) ? w0 : (z == 1) ? w1 : (z == 2) ? w2 : w3;
        __half* out = WT + (size_t)z * EMB * EMB;
        const int tx = tid & 31, ty = tid >> 5;
        const int xcol = bx * 32 + tx;
        const int y0 = by * 32;
        #pragma unroll
        for (int j = ty; j < 32; j += 8)
            t[j][tx] = in[(size_t)(y0 + j) * EMB + xcol];
        __syncthreads();
        const int ox = by * 32 + tx;
        const int oy0 = bx * 32;
        #pragma unroll
        for (int j = ty; j < 32; j += 8)
            out[(size_t)(oy0 + j) * EMB + ox] = __float2half_rn(t[tx][j]);
    } else {
        int i = (bid - 5120) * 256 + tid;   // 0..1535
        float v = (i < 512) ? bq[i] : ((i < 1024) ? bk[i - 512] : bv[i - 1024]);
        Bqkv[i] = v;
    }
}

// ---------------- host ----------------
extern "C" void kernel_launch(void* const* d_in, const int* in_sizes, int n_in,
                              void* d_out, int out_size)
{
    const float* x  = (const float*)d_in[0];
    const float* Wq = (const float*)d_in[1];
    const float* bq = (const float*)d_in[2];
    const float* Wk = (const float*)d_in[3];
    const float* bk = (const float*)d_in[4];
    const float* Wv = (const float*)d_in[5];
    const float* bv = (const float*)d_in[6];
    const float* Wo = (const float*)d_in[7];
    const float* bo = (const float*)d_in[8];
    float* out = (float*)d_out;

    __half *Xh, *QKV, *S, *O, *WT;
    float *Bqkv;
    cudaGetSymbolAddress((void**)&Xh,   g_Xh);
    cudaGetSymbolAddress((void**)&QKV,  g_QKV);
    cudaGetSymbolAddress((void**)&S,    g_S);
    cudaGetSymbolAddress((void**)&O,    g_O);
    cudaGetSymbolAddress((void**)&WT,   g_WT);
    cudaGetSymbolAddress((void**)&Bqkv, g_Bqkv);

    cudaFuncSetAttribute(gemm_nt<0, false>, cudaFuncAttributeMaxDynamicSharedMemorySize, SMEM_BYTES);
    cudaFuncSetAttribute(gemm_nt<1, false>, cudaFuncAttributeMaxDynamicSharedMemorySize, SMEM_BYTES);
    cudaFuncSetAttribute(gemm_nt<2, true>,  cudaFuncAttributeMaxDynamicSharedMemorySize, SMEM_BYTES);
    cudaFuncSetAttribute(gemm_nt<3, false>, cudaFuncAttributeMaxDynamicSharedMemorySize, SMEM_BYTES);

    const float scale = 0.044194173824159216f;  // 1/sqrt(512)
    const size_t W2 = (size_t)EMB * EMB;

    // Fused prep: x->fp16, weight transposes, bias concat (one launch)
    prep<<<5126, 256>>>(x, Xh, Wq, Wk, Wv, Wo, WT, bq, bk, bv, Bqkv);

    // Fused QKV projection: QKV[16384,1536] = Xh @ [Wq|Wk|Wv] + b -> fp16
    dim3 gqkv(3 * EMB / 128, TOK / 128, 1);
    gemm_nt<0, false><<<gqkv, 128, SMEM_BYTES>>>(
        Xh, WT, Bqkv, QKV, EMB, EMB, 3 * EMB, EMB, 0, 0, 0, 0, 1.0f);

    // Scores + fused exp + row partial sums: S = exp(scale * Q @ K^T) -> fp16
    dim3 gscore(SEQ / 128, SEQ / 128, BATCH);
    gemm_nt<1, false><<<gscore, 128, SMEM_BYTES>>>(
        QKV, QKV + EMB, nullptr, S, 3 * EMB, 3 * EMB, SEQ, EMB,
        (size_t)SEQ * 3 * EMB, (size_t)SEQ * 3 * EMB, (size_t)SEQ * SEQ, 0, scale);

    // O[b] = (S[b] @ V[b]) * invl[row] -> fp16 ; invl computed inline from
    // Lpart in the prologue (rowsum_final kernel eliminated). V read in
    // natural layout (B = QKV cols 1024..1535, [k][n] rows, trans-LDSM).
    dim3 gav(EMB / 128, SEQ / 128, BATCH);
    gemm_nt<2, true><<<gav, 128, SMEM_BYTES>>>(
        S, QKV + 2 * EMB, nullptr, O, SEQ, 3 * EMB, EMB, SEQ,
        (size_t)SEQ * SEQ, (size_t)SEQ * 3 * EMB, (size_t)SEQ * EMB, SEQ, 1.0f);

    // Final projection: out = O @ Wo + bo (fp32 out)
    dim3 gout(EMB / 128, TOK / 128, 1);
    gemm_nt<3, false><<<gout, 128, SMEM_BYTES>>>(
        O, WT + 3 * W2, bo, out, EMB, EMB, EMB, EMB, 0, 0, 0, 0, 1.0f);
}

// round 17
// speedup vs baseline: 1.0039x; 1.0039x over previous
#include <cuda_runtime.h>
#include <cuda_fp16.h>
#include <cstdint>

#define EMB 512
#define BATCH 8
#define SEQ 2048
#define TOK (BATCH * SEQ)   // 16384

// Scratch (allocation-free rule: __device__ globals)
__device__ __half g_Xh[(size_t)TOK * EMB];
__device__ __half g_QKV[(size_t)TOK * 3 * EMB];
__device__ __half g_O[(size_t)TOK * EMB];
__device__ __half g_S[(size_t)BATCH * SEQ * SEQ];
__device__ __half g_WT[4 * EMB * EMB];
__device__ float  g_Bqkv[3 * EMB];
__device__ float  g_Lpart[32 * TOK];
__device__ float  g_L[TOK];

// ---------------- PTX helpers (compute_103-safe) ----------------
__device__ __forceinline__ uint32_t smem_u32(const void* p) {
    uint32_t a;
    asm("{ .reg .u64 t; cvta.to.shared.u64 t, %1; cvt.u32.u64 %0, t; }" : "=r"(a) : "l"(p));
    return a;
}
__device__ __forceinline__ void cp16(uint32_t s, const void* g) {
    asm volatile("cp.async.cg.shared.global [%0], [%1], 16;" :: "r"(s), "l"(g));
}
#define CP_COMMIT() asm volatile("cp.async.commit_group;" ::: "memory")
#define CP_WAIT0()  asm volatile("cp.async.wait_group 0;" ::: "memory")

#define LDSM4(r0, r1, r2, r3, addr)                                            \
    asm volatile("ldmatrix.sync.aligned.m8n8.x4.shared.b16 {%0,%1,%2,%3}, [%4];" \
        : "=r"(r0), "=r"(r1), "=r"(r2), "=r"(r3) : "r"(addr))

#define LDSM4_T(r0, r1, r2, r3, addr)                                          \
    asm volatile("ldmatrix.sync.aligned.m8n8.x4.trans.shared.b16 {%0,%1,%2,%3}, [%4];" \
        : "=r"(r0), "=r"(r1), "=r"(r2), "=r"(r3) : "r"(addr))

// FMA-pipe exp (no MUFU): x ~ [-16,16], rel err ~2e-6.
__device__ __forceinline__ float fexp(float x) {
    float t = x * 1.4426950408889634f;
    float r = rintf(t);
    float f = t - r;
    float p =          1.3333558146428443e-3f;
    p = fmaf(p, f,     9.6181291076284772e-3f);
    p = fmaf(p, f,     5.5504108664821580e-2f);
    p = fmaf(p, f,     2.4022650695910071e-1f);
    p = fmaf(p, f,     6.9314718055994531e-1f);
    p = fmaf(p, f,     1.0f);
    int i = (int)r;
    return p * __int_as_float((i + 127) << 23);
}

// fp16 MMA m16n8k16, fp32 accumulate.
__device__ __forceinline__ void mma_f16(float* d, const uint32_t* a, uint32_t b0, uint32_t b1) {
    asm volatile(
        "mma.sync.aligned.m16n8k16.row.col.f32.f16.f16.f32 "
        "{%0,%1,%2,%3}, {%4,%5,%6,%7}, {%8,%9}, {%0,%1,%2,%3};"
        : "+f"(d[0]), "+f"(d[1]), "+f"(d[2]), "+f"(d[3])
        : "r"(a[0]), "r"(a[1]), "r"(a[2]), "r"(a[3]), "r"(b0), "r"(b1));
}

// ---------------- NT fp16 GEMM (ldmatrix, 64x64 warp tiles) ----------------
// C = scale * A @ B' (+epilogue). A [M,lda] halves, K-major.
// BTRANS=false: B [N,ldb] K-major (NT; non-trans LDSM, stride-72 smem).
// BTRANS=true:  B [K,ldb] N-major (NN; V's natural layout; trans LDSM,
//               stride-136 smem -> rows 272B apart, conflict-free).
// Block tile 128x128, BK=64, 4 warps (2x2), 2-stage cp.async, 2 CTAs/SM.
// EPI: 0 = +bias, ->half (QKV)   1 = exp, row-partial-sums, ->half (score)
//      2 = *invl[row], ->half (AV)   3 = +bias, ->float (final)
#define BK 64
#define STR 72
#define STRV 136
#define TILE_HALFS (128 * STR)               // 9216 (>= 64*136=8704 for BTRANS B)
#define STAGE_HALFS (2 * TILE_HALFS)         // 18432
#define SMEM_BYTES (2 * STAGE_HALFS * 2)     // 73728

template <int EPI, bool BTRANS>
__global__ void __launch_bounds__(128, 2) gemm_nt(
    const __half* __restrict__ A, const __half* __restrict__ B,
    const float* __restrict__ aux, void* __restrict__ Cv,
    int lda, int ldb, int ldc, int K,
    size_t sA, size_t sB, size_t sC, int sAux, float scale)
{
    extern __shared__ __half smem[];
    const uint32_t sbase = smem_u32(smem);

    const int tid  = threadIdx.x;
    const int lane = tid & 31;
    const int warp = tid >> 5;
    const int wr = (warp & 1) * 64;
    const int wc = (warp >> 1) * 64;

    const int b = blockIdx.z;
    A += (size_t)b * sA;
    B += (size_t)b * sB;
    if (aux) aux += (size_t)b * sAux;
    const int row0 = blockIdx.y * 128;
    const int col0 = blockIdx.x * 128;

    float acc[4][8][4];
    #pragma unroll
    for (int mi = 0; mi < 4; mi++)
        #pragma unroll
        for (int ni = 0; ni < 8; ni++)
            #pragma unroll
            for (int j = 0; j < 4; j++) acc[mi][ni][j] = 0.0f;

    const __half* gA = A + (size_t)row0 * lda;
    const __half* gB = BTRANS ? (B + col0) : (B + (size_t)col0 * ldb);

    auto fill = [&](int t, int buf) {
        uint32_t smA = sbase + (uint32_t)buf * STAGE_HALFS * 2;
        uint32_t smB = smA + TILE_HALFS * 2;
        const __half* pa = gA + t * BK;
        {   // A: 128 rows x 64 halves (128B rows)
            const int frow0 = tid >> 3;
            const int cq    = tid & 7;
            int row = frow0;
            #pragma unroll
            for (int it = 0; it < 8; it++, row += 16) {
                uint32_t off = 2u * (uint32_t)(row * STR + cq * 8);
                cp16(smA + off, pa + (size_t)row * lda + cq * 8);
            }
        }
        if (BTRANS) {
            // B: 64 k-rows x 128 halves (256B rows), stride STRV
            const __half* pb = B + (size_t)(t * BK) * ldb + col0;
            #pragma unroll
            for (int it = 0; it < 8; it++) {
                int idx = tid + it * 128;         // 0..1023
                int row = idx >> 4, cq = idx & 15;
                uint32_t off = 2u * (uint32_t)(row * STRV + cq * 8);
                cp16(smB + off, pb + (size_t)row * ldb + cq * 8);
            }
        } else {
            const __half* pb = gB + t * BK;
            const int frow0 = tid >> 3;
            const int cq    = tid & 7;
            int row = frow0;
            #pragma unroll
            for (int it = 0; it < 8; it++, row += 16) {
                uint32_t off = 2u * (uint32_t)(row * STR + cq * 8);
                cp16(smB + off, pb + (size_t)row * ldb + cq * 8);
            }
        }
    };

    const int ktiles = K / BK;
    fill(0, 0); CP_COMMIT();

    const int g = lane >> 2;
    const int q = lane & 3;
    const int l8 = lane & 7;
    const int jj = lane >> 3;

    uint32_t aOff[4];
    #pragma unroll
    for (int mi = 0; mi < 4; mi++) {
        int row = wr + mi * 16 + (jj & 1) * 8 + l8;
        aOff[mi] = 2u * (uint32_t)(row * STR + (jj >> 1) * 8);
    }
    // B fragment offsets: matrix j covers n in +(j>>1)*8, k in +(j&1)*8.
    uint32_t bOff[4];
    #pragma unroll
    for (int p = 0; p < 4; p++) {
        int nb = wc + p * 16 + (jj >> 1) * 8;
        if (BTRANS) {
            int krow = (jj & 1) * 8 + l8;
            bOff[p] = 2u * (uint32_t)(krow * STRV + nb);
        } else {
            bOff[p] = 2u * (uint32_t)((nb + l8) * STR + (jj & 1) * 8);
        }
    }

    for (int t = 0; t < ktiles; t++) {
        CP_WAIT0();
        __syncthreads();
        if (t + 1 < ktiles) { fill(t + 1, (t + 1) & 1); CP_COMMIT(); }

        const uint32_t smA = sbase + (uint32_t)(t & 1) * STAGE_HALFS * 2;
        const uint32_t smB = smA + TILE_HALFS * 2;

        #pragma unroll
        for (int ks = 0; ks < 4; ks++) {
            const uint32_t kaddA = (uint32_t)ks * 32;            // 16 halves
            const uint32_t kaddB = BTRANS ? (uint32_t)ks * STRV * 32 : (uint32_t)ks * 32;
            uint32_t a[4][4], bb[4][4];
            #pragma unroll
            for (int mi = 0; mi < 4; mi++)
                LDSM4(a[mi][0], a[mi][1], a[mi][2], a[mi][3], smA + aOff[mi] + kaddA);
            #pragma unroll
            for (int p = 0; p < 4; p++) {
                if (BTRANS) LDSM4_T(bb[p][0], bb[p][1], bb[p][2], bb[p][3], smB + bOff[p] + kaddB);
                else        LDSM4  (bb[p][0], bb[p][1], bb[p][2], bb[p][3], smB + bOff[p] + kaddB);
            }
            #pragma unroll
            for (int p = 0; p < 4; p++)
                #pragma unroll
                for (int mi = 0; mi < 4; mi++) {
                    mma_f16(acc[mi][2 * p],     a[mi], bb[p][0], bb[p][1]);
                    mma_f16(acc[mi][2 * p + 1], a[mi], bb[p][2], bb[p][3]);
                }
        }
    }

    // Epilogue
    float rs0[4], rs1[4];
    #pragma unroll
    for (int mi = 0; mi < 4; mi++) { rs0[mi] = 0.0f; rs1[mi] = 0.0f; }

    #pragma unroll
    for (int mi = 0; mi < 4; mi++) {
        int rloc = wr + mi * 16 + g;
        int r = row0 + rloc;
        float il0 = 1.0f, il1 = 1.0f;
        if (EPI == 2) { il0 = aux[r]; il1 = aux[r + 8]; }
        #pragma unroll
        for (int ni = 0; ni < 8; ni++) {
            int c = wc + ni * 8 + 2 * q;
            float2 v0, v1;
            v0.x = acc[mi][ni][0] * scale;
            v0.y = acc[mi][ni][1] * scale;
            v1.x = acc[mi][ni][2] * scale;
            v1.y = acc[mi][ni][3] * scale;
            if (EPI == 0 || EPI == 3) {
                float bx = aux[col0 + c], by = aux[col0 + c + 1];
                v0.x += bx; v0.y += by;
                v1.x += bx; v1.y += by;
            }
            if (EPI == 1) {
                v0.x = fexp(v0.x); v0.y = fexp(v0.y);
                v1.x = fexp(v1.x); v1.y = fexp(v1.y);
                rs0[mi] += v0.x + v0.y;
                rs1[mi] += v1.x + v1.y;
            }
            if (EPI == 2) {
                v0.x *= il0; v0.y *= il0;
                v1.x *= il1; v1.y *= il1;
            }
            if (EPI == 3) {
                float* c0 = (float*)Cv + (size_t)b * sC + (size_t)r * ldc + col0;
                float* c1 = c0 + (size_t)8 * ldc;
                *reinterpret_cast<float2*>(c0 + c) = v0;
                *reinterpret_cast<float2*>(c1 + c) = v1;
            } else {
                __half* c0 = (__half*)Cv + (size_t)b * sC + (size_t)r * ldc + col0;
                __half* c1 = c0 + (size_t)8 * ldc;
                *reinterpret_cast<__half2*>(c0 + c) = __floats2half2_rn(v0.x, v0.y);
                *reinterpret_cast<__half2*>(c1 + c) = __floats2half2_rn(v1.x, v1.y);
            }
        }
    }

    if (EPI == 1) {
        #pragma unroll
        for (int mi = 0; mi < 4; mi++) {
            rs0[mi] += __shfl_xor_sync(0xFFFFFFFF, rs0[mi], 1);
            rs0[mi] += __shfl_xor_sync(0xFFFFFFFF, rs0[mi], 2);
            rs1[mi] += __shfl_xor_sync(0xFFFFFFFF, rs1[mi], 1);
            rs1[mi] += __shfl_xor_sync(0xFFFFFFFF, rs1[mi], 2);
        }
        if (q == 0) {
            int slot = blockIdx.x * 2 + (warp >> 1);
            size_t base = (size_t)slot * TOK + (size_t)b * SEQ + row0 + wr;
            #pragma unroll
            for (int mi = 0; mi < 4; mi++) {
                g_Lpart[base + mi * 16 + g]     = rs0[mi];
                g_Lpart[base + mi * 16 + g + 8] = rs1[mi];
            }
        }
    }
}

// ---------------- row-sum finalize: invl[r] = 1 / sum_32 Lpart ----------------
__global__ void __launch_bounds__(128) rowsum_final(
    const float* __restrict__ LP, float* __restrict__ invl)
{
    int r = blockIdx.x * 128 + threadIdx.x;
    float s = 0.0f;
    #pragma unroll
    for (int i = 0; i < 32; i++) s += LP[(size_t)i * TOK + r];
    invl[r] = 1.0f / s;
}

// -------- fused prep: x->fp16 copy, 4 weight transposes, bias concat --------
// grid layout (flat blockIdx.x, 256 threads):
//   [0, 2048)        : round_h   (16 floats/thread)
//   [2048, 3072)     : transpose 32x32 tiles of W[z] (z = block/256)
//   [3072, 3078)     : concat_bias
__global__ void __launch_bounds__(256) prep(
    const float* __restrict__ x, __half* __restrict__ Xh,
    const float* __restrict__ w0, const float* __restrict__ w1,
    const float* __restrict__ w2, const float* __restrict__ w3,
    __half* __restrict__ WT,
    const float* __restrict__ bq, const float* __restrict__ bk,
    const float* __restrict__ bv, float* __restrict__ Bqkv)
{
    __shared__ float t[32][33];
    const int bid = blockIdx.x;
    const int tid = threadIdx.x;

    if (bid < 2048) {
        size_t i = ((size_t)bid * 256 + tid) * 8;
        const size_t stride = (size_t)2048 * 256 * 8;
        #pragma unroll
        for (int rep = 0; rep < 2; rep++, i += stride) {
            float4 v0 = *reinterpret_cast<const float4*>(x + i);
            float4 v1 = *reinterpret_cast<const float4*>(x + i + 4);
            __half2 h[4];
            h[0] = __floats2half2_rn(v0.x, v0.y);
            h[1] = __floats2half2_rn(v0.z, v0.w);
            h[2] = __floats2half2_rn(v1.x, v1.y);
            h[3] = __floats2half2_rn(v1.z, v1.w);
            *reinterpret_cast<uint4*>(Xh + i) = *reinterpret_cast<uint4*>(h);
        }
    } else if (bid < 3072) {
        int b2 = bid - 2048;
        int z = b2 >> 8;
        int rem = b2 & 255;
        int bx = rem & 15, by = rem >> 4;
        const float* in = (z == 0) ? w0 : (z == 1) ? w1 : (z == 2) ? w2 : w3;
        __half* out = WT + (size_t)z * EMB * EMB;
        const int tx = tid & 31, ty = tid >> 5;
        const int xcol = bx * 32 + tx;
        const int y0 = by * 32;
        #pragma unroll
        for (int j = ty; j < 32; j += 8)
            t[j][tx] = in[(size_t)(y0 + j) * EMB + xcol];
        __syncthreads();
        const int ox = by * 32 + tx;
        const int oy0 = bx * 32;
        #pragma unroll
        for (int j = ty; j < 32; j += 8)
            out[(size_t)(oy0 + j) * EMB + ox] = __float2half_rn(t[tx][j]);
    } else {
        int i = (bid - 3072) * 256 + tid;   // 0..1535
        float v = (i < 512) ? bq[i] : ((i < 1024) ? bk[i - 512] : bv[i - 1024]);
        Bqkv[i] = v;
    }
}

// ---------------- host ----------------
extern "C" void kernel_launch(void* const* d_in, const int* in_sizes, int n_in,
                              void* d_out, int out_size)
{
    const float* x  = (const float*)d_in[0];
    const float* Wq = (const float*)d_in[1];
    const float* bq = (const float*)d_in[2];
    const float* Wk = (const float*)d_in[3];
    const float* bk = (const float*)d_in[4];
    const float* Wv = (const float*)d_in[5];
    const float* bv = (const float*)d_in[6];
    const float* Wo = (const float*)d_in[7];
    const float* bo = (const float*)d_in[8];
    float* out = (float*)d_out;

    __half *Xh, *QKV, *S, *O, *WT;
    float *Bqkv, *LP, *L;
    cudaGetSymbolAddress((void**)&Xh,   g_Xh);
    cudaGetSymbolAddress((void**)&QKV,  g_QKV);
    cudaGetSymbolAddress((void**)&S,    g_S);
    cudaGetSymbolAddress((void**)&O,    g_O);
    cudaGetSymbolAddress((void**)&WT,   g_WT);
    cudaGetSymbolAddress((void**)&Bqkv, g_Bqkv);
    cudaGetSymbolAddress((void**)&LP,   g_Lpart);
    cudaGetSymbolAddress((void**)&L,    g_L);

    cudaFuncSetAttribute(gemm_nt<0, false>, cudaFuncAttributeMaxDynamicSharedMemorySize, SMEM_BYTES);
    cudaFuncSetAttribute(gemm_nt<1, false>, cudaFuncAttributeMaxDynamicSharedMemorySize, SMEM_BYTES);
    cudaFuncSetAttribute(gemm_nt<2, true>,  cudaFuncAttributeMaxDynamicSharedMemorySize, SMEM_BYTES);
    cudaFuncSetAttribute(gemm_nt<3, false>, cudaFuncAttributeMaxDynamicSharedMemorySize, SMEM_BYTES);

    const float scale = 0.044194173824159216f;  // 1/sqrt(512)
    const size_t W2 = (size_t)EMB * EMB;

    // Fused prep: x->fp16, weight transposes, bias concat (one launch)
    prep<<<3078, 256>>>(x, Xh, Wq, Wk, Wv, Wo, WT, bq, bk, bv, Bqkv);

    // Fused QKV projection: QKV[16384,1536] = Xh @ [Wq|Wk|Wv] + b -> fp16
    dim3 gqkv(3 * EMB / 128, TOK / 128, 1);
    gemm_nt<0, false><<<gqkv, 128, SMEM_BYTES>>>(
        Xh, WT, Bqkv, QKV, EMB, EMB, 3 * EMB, EMB, 0, 0, 0, 0, 1.0f);

    // Scores + fused exp + row partial sums: S = exp(scale * Q @ K^T) -> fp16
    dim3 gscore(SEQ / 128, SEQ / 128, BATCH);
    gemm_nt<1, false><<<gscore, 128, SMEM_BYTES>>>(
        QKV, QKV + EMB, nullptr, S, 3 * EMB, 3 * EMB, SEQ, EMB,
        (size_t)SEQ * 3 * EMB, (size_t)SEQ * 3 * EMB, (size_t)SEQ * SEQ, 0, scale);

    // invl[r] = 1 / sum(exp row)
    rowsum_final<<<TOK / 128, 128>>>(LP, L);

    // O[b] = (S[b] @ V[b]) * invl[row] -> fp16 ; V read in natural layout
    // (B = QKV cols 1024..1535, [k][n] rows, trans-LDSM)
    dim3 gav(EMB / 128, SEQ / 128, BATCH);
    gemm_nt<2, true><<<gav, 128, SMEM_BYTES>>>(
        S, QKV + 2 * EMB, L, O, SEQ, 3 * EMB, EMB, SEQ,
        (size_t)SEQ * SEQ, (size_t)SEQ * 3 * EMB, (size_t)SEQ * EMB, SEQ, 1.0f);

    // Final projection: out = O @ Wo + bo (fp32 out)
    dim3 gout(EMB / 128, TOK / 128, 1);
    gemm_nt<3, false><<<gout, 128, SMEM_BYTES>>>(
        O, WT + 3 * W2, bo, out, EMB, EMB, EMB, EMB, 0, 0, 0, 0, 1.0f);
}